// round 7
// baseline (speedup 1.0000x reference)
#include <cuda_runtime.h>
#include <cstdint>
#include <cstddef>
#include <math.h>

#define D_DIM 2048
#define E_DIM 64
#define TM    64
#define BK    32
#define NTHREADS 128
#define TOPK  8
#define GRP   8

typedef unsigned long long u64;

// Packed dual-FMA (Blackwell f32x2): d = a*b + c on two packed fp32 lanes.
__device__ __forceinline__ u64 ffma2(u64 a, u64 b, u64 c) {
    u64 d;
    asm("fma.rn.f32x2 %0, %1, %2, %3;" : "=l"(d) : "l"(a), "l"(b), "l"(c));
    return d;
}
__device__ __forceinline__ u64 fadd2(u64 a, u64 b) {
    u64 d;
    asm("add.rn.f32x2 %0, %1, %2;" : "=l"(d) : "l"(a), "l"(b));
    return d;
}
__device__ __forceinline__ u64 dup_f32(float v) {
    unsigned int u = __float_as_uint(v);
    return ((u64)u << 32) | (u64)u;
}

#define NEG1_DUP 0xBF800000BF800000ULL

__global__ __launch_bounds__(NTHREADS, 2)
void router_gemm_softmax_topk(const float* __restrict__ h,
                              const float* __restrict__ W,
                              const float* __restrict__ cal_scale,
                              const float* __restrict__ cal_bias,
                              float* __restrict__ out,
                              int T) {
    __shared__ union SmemU {
        struct {
            float A[2][BK][TM];     // transposed: [k][token]      16 KB
            float B[2][BK][E_DIM];  // natural:    [k][expert]     16 KB
        } mm;
        float L[TM][E_DIM + 1];     // logits/probs, padded
    } sm;

    const int tid = threadIdx.x;
    const int s   = tid & 7;    // token slot: tokens 4s..4s+3 and 32+4s..32+4s+3
    const int eg  = tid >> 3;   // expert group 0..15: experts 4eg..4eg+3
    const int t0  = blockIdx.x * TM;

    // global-load roles
    const int tr = tid & 63;    // token row for A load (also expert row for B)
    const int kh = tid >> 6;    // 16-wide k-half (0/1)

    const float* hrow = h + (size_t)(t0 + tr) * D_DIM + 16 * kh;
    const float* wrow = W + (size_t)tr * D_DIM + 16 * kh;

    // 4 token-pairs x 4 experts
    u64 acc[4][4], cmp[4][4];
#pragma unroll
    for (int j = 0; j < 4; j++)
#pragma unroll
        for (int i = 0; i < 4; i++) { acc[j][i] = 0ULL; cmp[j][i] = 0ULL; }

    float4 a4[4];
    float4 b4[4];

    auto ldg_chunk = [&](int c) {
        const float4* ap = reinterpret_cast<const float4*>(hrow + c * BK);
#pragma unroll
        for (int q = 0; q < 4; q++) a4[q] = ap[q];
        const float4* bp = reinterpret_cast<const float4*>(wrow + c * BK);
#pragma unroll
        for (int q = 0; q < 4; q++) b4[q] = bp[q];
    };

    auto sts_chunk = [&](int buf) {
#pragma unroll
        for (int q = 0; q < 4; q++) {
            int kb = 16 * kh + 4 * q;
            sm.mm.A[buf][kb + 0][tr] = a4[q].x;
            sm.mm.A[buf][kb + 1][tr] = a4[q].y;
            sm.mm.A[buf][kb + 2][tr] = a4[q].z;
            sm.mm.A[buf][kb + 3][tr] = a4[q].w;
            sm.mm.B[buf][kb + 0][tr] = b4[q].x;
            sm.mm.B[buf][kb + 1][tr] = b4[q].y;
            sm.mm.B[buf][kb + 2][tr] = b4[q].z;
            sm.mm.B[buf][kb + 3][tr] = b4[q].w;
        }
    };

    // prologue
    ldg_chunk(0);
    sts_chunk(0);
    __syncthreads();

    const int NC = D_DIM / BK;  // 64 chunks
    for (int c = 0; c < NC; c++) {
        const int buf = c & 1;
        if (c + 1 < NC) ldg_chunk(c + 1);

#pragma unroll
        for (int g = 0; g < BK / GRP; g++) {   // 4 groups of 8 k-steps
            u64 y[4][4];
#pragma unroll
            for (int kk = 0; kk < GRP; kk++) {
                const int k = GRP * g + kk;
                // A: 8 tokens = 4 packed pairs (two LDS.128)
                ulonglong2 aA = *reinterpret_cast<const ulonglong2*>(
                    &sm.mm.A[buf][k][4 * s]);
                ulonglong2 aB = *reinterpret_cast<const ulonglong2*>(
                    &sm.mm.A[buf][k][32 + 4 * s]);
                u64 a[4] = {aA.x, aA.y, aB.x, aB.y};
                // B: 4 experts, one LDS.128, duplicate in registers
                float4 bf = *reinterpret_cast<const float4*>(
                    &sm.mm.B[buf][k][4 * eg]);
                u64 bd[4] = {dup_f32(bf.x), dup_f32(bf.y),
                             dup_f32(bf.z), dup_f32(bf.w)};
                if (kk == 0) {
                    // seed group chain with pending correction (-c)
#pragma unroll
                    for (int j = 0; j < 4; j++)
#pragma unroll
                        for (int i = 0; i < 4; i++)
                            y[j][i] = ffma2(a[j], bd[i], cmp[j][i]);
                } else {
#pragma unroll
                    for (int j = 0; j < 4; j++)
#pragma unroll
                        for (int i = 0; i < 4; i++)
                            y[j][i] = ffma2(a[j], bd[i], y[j][i]);
                }
            }
            // Fast2Sum merge of group sum y into (acc, cmp)
#pragma unroll
            for (int j = 0; j < 4; j++)
#pragma unroll
                for (int i = 0; i < 4; i++) {
                    u64 t = fadd2(acc[j][i], y[j][i]);
                    u64 z = ffma2(t, NEG1_DUP, acc[j][i]);  // acc - t
                    cmp[j][i] = fadd2(z, y[j][i]);          // -c_new
                    acc[j][i] = t;
                }
        }

        if (c + 1 < NC) sts_chunk(buf ^ 1);  // other buffer: safe vs current compute
        __syncthreads();
    }

    // ---- epilogue: finish compensation, calibrate, scatter logits to smem ----
    float sc[4], bs[4];
#pragma unroll
    for (int i = 0; i < 4; i++) {
        sc[i] = cal_scale[4 * eg + i];
        bs[i] = cal_bias[4 * eg + i];
    }
#pragma unroll
    for (int j = 0; j < 4; j++) {
        // pair j covers tokens: base + {0,1}
        int tA = (j & 2 ? 32 : 0) + 4 * s + (j & 1 ? 2 : 0);
#pragma unroll
        for (int i = 0; i < 4; i++) {
            u64 v = fadd2(acc[j][i], cmp[j][i]);
            float lo = __uint_as_float((unsigned int)(v & 0xffffffffULL));
            float hi = __uint_as_float((unsigned int)(v >> 32));
            sm.L[tA + 0][4 * eg + i] = fmaf(lo, sc[i], bs[i]);
            sm.L[tA + 1][4 * eg + i] = fmaf(hi, sc[i], bs[i]);
        }
    }
    __syncthreads();

    // ---- per-token softmax + top-8 (one thread per token, tid < 64) ----
    if (tid < TM) {
        const int t = tid;
        float* row = sm.L[t];
        float m = row[0];
#pragma unroll 8
        for (int e = 1; e < E_DIM; e++) m = fmaxf(m, row[e]);
        float ssum = 0.0f;
#pragma unroll 8
        for (int e = 0; e < E_DIM; e++) {
            float p = expf(row[e] - m);
            row[e] = p;
            ssum += p;
        }
        float inv = 1.0f / ssum;
        float* oprob = out + (size_t)(t0 + t) * E_DIM;
#pragma unroll 8
        for (int e = 0; e < E_DIM; e++) {
            float p = row[e] * inv;
            row[e] = p;
            oprob[e] = p;
        }

        const size_t base_w = (size_t)T * E_DIM;
        const size_t base_i = base_w + (size_t)T * TOPK;
        u64 used = 0ULL;
#pragma unroll
        for (int r = 0; r < TOPK; r++) {
            float bv = -1.0f;
            int   bi = 0;
            for (int e = 0; e < E_DIM; e++) {
                bool ok = !((used >> e) & 1ULL);
                float p = row[e];
                if (ok && p > bv) { bv = p; bi = e; }
            }
            used |= 1ULL << bi;
            out[base_w + (size_t)(t0 + t) * TOPK + r] = bv;
            out[base_i + (size_t)(t0 + t) * TOPK + r] = (float)bi;
        }
    }
}

extern "C" void kernel_launch(void* const* d_in, const int* in_sizes, int n_in,
                              void* d_out, int out_size) {
    const float* h  = (const float*)d_in[0];
    const float* W  = (const float*)d_in[1];
    const float* cs = (const float*)d_in[2];
    const float* cb = (const float*)d_in[3];
    float* out = (float*)d_out;

    int T  = in_sizes[0] / D_DIM;   // 16384
    int nb = T / TM;                // 256 blocks
    router_gemm_softmax_topk<<<nb, NTHREADS>>>(h, W, cs, cb, out, T);
}

// round 8
// speedup vs baseline: 1.0943x; 1.0943x over previous
#include <cuda_runtime.h>
#include <cstdint>
#include <cstddef>
#include <math.h>

#define D_DIM 2048
#define E_DIM 64
#define TM    128
#define BK    32
#define NTHREADS 256
#define TOPK  8

typedef unsigned long long u64;

// Packed dual ops (Blackwell f32x2)
__device__ __forceinline__ u64 ffma2(u64 a, u64 b, u64 c) {
    u64 d;
    asm("fma.rn.f32x2 %0, %1, %2, %3;" : "=l"(d) : "l"(a), "l"(b), "l"(c));
    return d;
}
__device__ __forceinline__ u64 fmul2(u64 a, u64 b) {
    u64 d;
    asm("mul.rn.f32x2 %0, %1, %2;" : "=l"(d) : "l"(a), "l"(b));
    return d;
}
__device__ __forceinline__ u64 fadd2(u64 a, u64 b) {
    u64 d;
    asm("add.rn.f32x2 %0, %1, %2;" : "=l"(d) : "l"(a), "l"(b));
    return d;
}
__device__ __forceinline__ u64 dup_f32(float v) {
    unsigned int u = __float_as_uint(v);
    return ((u64)u << 32) | (u64)u;
}

__global__ __launch_bounds__(NTHREADS, 1)
void router_gemm_softmax_topk(const float* __restrict__ h,
                              const float* __restrict__ W,
                              const float* __restrict__ cal_scale,
                              const float* __restrict__ cal_bias,
                              float* __restrict__ out,
                              int T) {
    __shared__ union SmemU {
        struct {
            float A[2][BK][TM];     // transposed: [k][token]      32 KB
            float B[2][BK][E_DIM];  // natural:    [k][expert]     16 KB
        } mm;
        float L[TM][E_DIM + 1];     // logits/probs, padded        33 KB
    } sm;

    const int tid = threadIdx.x;
    const int s   = tid & 15;   // token slot: tokens 4s..4s+3 and 64+4s..64+4s+3
    const int eg  = tid >> 4;   // expert group 0..15: experts 4eg..4eg+3
    const int t0  = blockIdx.x * TM;

    // global-load roles
    const int tr = tid & 127;   // token row for A load
    const int kh = tid >> 7;    // 16-wide k-half (0/1)
    const int be = tid & 63;    // expert row for B load
    const int ks = tid >> 6;    // 8-wide k-quarter (0..3)

    const float* hrow = h + (size_t)(t0 + tr) * D_DIM + 16 * kh;
    const float* wrow = W + (size_t)be * D_DIM + 8 * ks;

    // level-2 accumulators: 4 token-pairs x 4 experts
    u64 acc[4][4];
#pragma unroll
    for (int j = 0; j < 4; j++)
#pragma unroll
        for (int i = 0; i < 4; i++) acc[j][i] = 0ULL;

    float4 a4[4];
    float4 b4[2];

    auto ldg_chunk = [&](int c) {
        const float4* ap = reinterpret_cast<const float4*>(hrow + c * BK);
#pragma unroll
        for (int q = 0; q < 4; q++) a4[q] = ap[q];
        const float4* bp = reinterpret_cast<const float4*>(wrow + c * BK);
        b4[0] = bp[0];
        b4[1] = bp[1];
    };

    auto sts_chunk = [&](int buf) {
#pragma unroll
        for (int q = 0; q < 4; q++) {
            int kb = 16 * kh + 4 * q;
            sm.mm.A[buf][kb + 0][tr] = a4[q].x;
            sm.mm.A[buf][kb + 1][tr] = a4[q].y;
            sm.mm.A[buf][kb + 2][tr] = a4[q].z;
            sm.mm.A[buf][kb + 3][tr] = a4[q].w;
        }
#pragma unroll
        for (int q = 0; q < 2; q++) {
            int kb = 8 * ks + 4 * q;
            sm.mm.B[buf][kb + 0][be] = (q ? b4[1].x : b4[0].x);
            sm.mm.B[buf][kb + 1][be] = (q ? b4[1].y : b4[0].y);
            sm.mm.B[buf][kb + 2][be] = (q ? b4[1].z : b4[0].z);
            sm.mm.B[buf][kb + 3][be] = (q ? b4[1].w : b4[0].w);
        }
    };

    // prologue
    ldg_chunk(0);
    sts_chunk(0);
    __syncthreads();

    const int NC = D_DIM / BK;  // 64 chunks
    for (int c = 0; c < NC; c++) {
        const int buf = c & 1;
        if (c + 1 < NC) ldg_chunk(c + 1);

        // level-1: plain 32-deep FMA2 chain per accumulator (chunk partial)
        u64 y[4][4];
#pragma unroll
        for (int k = 0; k < BK; k++) {
            // A: 8 tokens = 4 packed pairs (two LDS.128)
            ulonglong2 aA = *reinterpret_cast<const ulonglong2*>(
                &sm.mm.A[buf][k][4 * s]);
            ulonglong2 aB = *reinterpret_cast<const ulonglong2*>(
                &sm.mm.A[buf][k][64 + 4 * s]);
            u64 a[4] = {aA.x, aA.y, aB.x, aB.y};
            // B: 4 experts, one LDS.128, duplicate in registers
            float4 bf = *reinterpret_cast<const float4*>(
                &sm.mm.B[buf][k][4 * eg]);
            u64 bd[4] = {dup_f32(bf.x), dup_f32(bf.y),
                         dup_f32(bf.z), dup_f32(bf.w)};
            if (k == 0) {
#pragma unroll
                for (int j = 0; j < 4; j++)
#pragma unroll
                    for (int i = 0; i < 4; i++)
                        y[j][i] = fmul2(a[j], bd[i]);
            } else {
#pragma unroll
                for (int j = 0; j < 4; j++)
#pragma unroll
                    for (int i = 0; i < 4; i++)
                        y[j][i] = ffma2(a[j], bd[i], y[j][i]);
            }
        }
        // level-2 cascade: one add per accumulator per chunk
#pragma unroll
        for (int j = 0; j < 4; j++)
#pragma unroll
            for (int i = 0; i < 4; i++)
                acc[j][i] = fadd2(acc[j][i], y[j][i]);

        if (c + 1 < NC) sts_chunk(buf ^ 1);  // other buffer: safe vs current compute
        __syncthreads();
    }

    // ---- epilogue: calibrate, scatter logits to smem ----
    float sc[4], bs[4];
#pragma unroll
    for (int i = 0; i < 4; i++) {
        sc[i] = cal_scale[4 * eg + i];
        bs[i] = cal_bias[4 * eg + i];
    }
#pragma unroll
    for (int j = 0; j < 4; j++) {
        int tA = (j & 2 ? 64 : 0) + 4 * s + (j & 1 ? 2 : 0);
#pragma unroll
        for (int i = 0; i < 4; i++) {
            u64 v = acc[j][i];
            float lo = __uint_as_float((unsigned int)(v & 0xffffffffULL));
            float hi = __uint_as_float((unsigned int)(v >> 32));
            sm.L[tA + 0][4 * eg + i] = fmaf(lo, sc[i], bs[i]);
            sm.L[tA + 1][4 * eg + i] = fmaf(hi, sc[i], bs[i]);
        }
    }
    __syncthreads();

    // ---- per-token softmax + top-8 (one thread per token, tid < 128) ----
    if (tid < TM) {
        const int t = tid;
        float* row = sm.L[t];
        float m = row[0];
#pragma unroll 8
        for (int e = 1; e < E_DIM; e++) m = fmaxf(m, row[e]);
        float ssum = 0.0f;
#pragma unroll 8
        for (int e = 0; e < E_DIM; e++) {
            float p = expf(row[e] - m);
            row[e] = p;
            ssum += p;
        }
        float inv = 1.0f / ssum;
        float* oprob = out + (size_t)(t0 + t) * E_DIM;
#pragma unroll 8
        for (int e = 0; e < E_DIM; e++) {
            float p = row[e] * inv;
            row[e] = p;
            oprob[e] = p;
        }

        const size_t base_w = (size_t)T * E_DIM;
        const size_t base_i = base_w + (size_t)T * TOPK;
        u64 used = 0ULL;
#pragma unroll
        for (int r = 0; r < TOPK; r++) {
            float bv = -1.0f;
            int   bi = 0;
            for (int e = 0; e < E_DIM; e++) {
                bool ok = !((used >> e) & 1ULL);
                float p = row[e];
                if (ok && p > bv) { bv = p; bi = e; }
            }
            used |= 1ULL << bi;
            out[base_w + (size_t)(t0 + t) * TOPK + r] = bv;
            out[base_i + (size_t)(t0 + t) * TOPK + r] = (float)bi;
        }
    }
}

extern "C" void kernel_launch(void* const* d_in, const int* in_sizes, int n_in,
                              void* d_out, int out_size) {
    const float* h  = (const float*)d_in[0];
    const float* W  = (const float*)d_in[1];
    const float* cs = (const float*)d_in[2];
    const float* cb = (const float*)d_in[3];
    float* out = (float*)d_out;

    int T  = in_sizes[0] / D_DIM;   // 16384
    int nb = T / TM;                // 128 blocks
    router_gemm_softmax_topk<<<nb, NTHREADS>>>(h, W, cs, cb, out, T);
}